// round 1
// baseline (speedup 1.0000x reference)
#include <cuda_runtime.h>
#include <cuda_bf16.h>
#include <math.h>

// Problem constants
#define BB 2
#define QQ 4096
#define CC 64
#define HH 64
#define WW 64
#define CK 576          // C*9
#define KIN 580         // CK + 4
#define KINP 584        // padded to multiple of 8
#define HID 256
#define NROW (BB*QQ)        // 8192
#define NROW4 (BB*QQ*4)     // 32768

// ---------------- scratch (device globals; no allocation) ----------------
__device__ float g_INP[NROW4 * KINP];     // [32768, 584]  (cols 576..579 = rel/scale, 580..583 = 0)
__device__ float g_QRY[NROW * CK];        // [8192, 576]
__device__ float g_Hk [NROW4 * HID];
__device__ float g_Hv [NROW4 * HID];
__device__ float g_PK [NROW4 * CK];
__device__ float g_PV [NROW4 * CK];
__device__ float g_X  [NROW * CK];
__device__ float g_Hq [NROW * HID];
__device__ float g_kW1p[KINP * HID];
__device__ float g_vW1p[KINP * HID];

// ---------------- weight padding: [580,256] -> [584,256] with zero rows ----
__global__ void pad_w1_kernel(const float* __restrict__ kW1, const float* __restrict__ vW1) {
    int i = blockIdx.x * 256 + threadIdx.x;
    if (i < KINP * HID) {
        int r = i / HID, c = i - r * HID;
        float kv = 0.f, vv = 0.f;
        if (r < KIN) { kv = kW1[r * HID + c]; vv = vW1[r * HID + c]; }
        g_kW1p[i] = kv;
        g_vW1p[i] = vv;
    }
}

// ---------------- setup: gather unfold samples, build INP + query ----------
__device__ __forceinline__ int nearest_idx(float c) {
    // floor(((c+1)*64 - 1)*0.5 + 0.5), clamped to [0,63]
    float f = ((c + 1.0f) * 64.0f - 1.0f) * 0.5f + 0.5f;
    int i = (int)floorf(f);
    return i < 0 ? 0 : (i > 63 ? 63 : i);
}

__global__ __launch_bounds__(128) void setup_kernel(
    const float* __restrict__ feature,   // [B,C,H,W]
    const float* __restrict__ coord,     // [B,Q,2]
    const float* __restrict__ scale)     // [B,Q,2]
{
    const int bq = blockIdx.x;
    const int b  = bq >> 12;       // /4096
    const int tid = threadIdx.x;

    const float cy = coord[bq * 2 + 0];
    const float cx = coord[bq * 2 + 1];
    const float s0 = scale[bq * 2 + 0];
    const float s1 = scale[bq * 2 + 1];
    const float lo = -1.0f + 1e-6f, hi = 1.0f - 1e-6f;

    // ---- query shifts (local ensemble) ----
    int   qy[4], qx[4];
    float area[4];
    const float rx = 1.0f / 64.0f, ry = 1.0f / 64.0f;
    #pragma unroll
    for (int s = 0; s < 4; s++) {
        float vx = (s >= 2) ? 1.0f : -1.0f;
        float vy = (s & 1)  ? 1.0f : -1.0f;
        float c0 = fminf(fmaxf(cy + vx * rx + 1e-6f, lo), hi);
        float c1 = fminf(fmaxf(cx + vy * ry + 1e-6f, lo), hi);
        int iy = nearest_idx(c0), ix = nearest_idx(c1);
        qy[s] = iy; qx[s] = ix;
        float qc0 = -1.0f + (2.0f * iy + 1.0f) / 64.0f;
        float qc1 = -1.0f + (2.0f * ix + 1.0f) / 64.0f;
        float r0 = (cy - qc0) * 64.0f;
        float r1 = (cx - qc1) * 64.0f;
        area[s] = fabsf(r0 * r1) + 1e-9f;
    }
    float tot = area[0] + area[1] + area[2] + area[3];
    float qw[4];
    #pragma unroll
    for (int s = 0; s < 4; s++) qw[s] = area[3 - s] / tot;   // diagonal swap

    // ---- key/value shifts ----
    const float sc00 = scale[(b * QQ) * 2 + 0];
    const float sc01 = scale[(b * QQ) * 2 + 1];
    const float invtx = (1.0f - sc00) / 63.0f;   // 1/tx
    const float invty = (1.0f - sc01) / 63.0f;
    int   ky[4], kx[4];
    float kr0[4], kr1[4];
    #pragma unroll
    for (int s = 0; s < 4; s++) {
        float vx = (s >= 2) ? 1.0f : -1.0f;
        float vy = (s & 1)  ? 1.0f : -1.0f;
        float c0 = fminf(fmaxf(cy + vx * invtx + 1e-6f, lo), hi);
        float c1 = fminf(fmaxf(cx + vy * invty + 1e-6f, lo), hi);
        int iy = nearest_idx(c0), ix = nearest_idx(c1);
        ky[s] = iy; kx[s] = ix;
        float qc0 = -1.0f + (2.0f * iy + 1.0f) / 64.0f;
        float qc1 = -1.0f + (2.0f * ix + 1.0f) / 64.0f;
        kr0[s] = (cy - qc0) * 64.0f;
        kr1[s] = (cx - qc1) * 64.0f;
    }

    // ---- gather 3x3 neighborhoods ----
    const float* fb = feature + (size_t)b * CC * HH * WW;
    for (int k = tid; k < CK; k += 128) {
        int c = k / 9, p = k - c * 9;
        int di = p / 3 - 1, dj = p - (p / 3) * 3 - 1;
        const float* fc = fb + (size_t)c * (HH * WW);
        float qacc = 0.f;
        #pragma unroll
        for (int s = 0; s < 4; s++) {
            int y = qy[s] + di, x = qx[s] + dj;
            float v = ((unsigned)y < 64u && (unsigned)x < 64u) ? fc[y * 64 + x] : 0.f;
            qacc += qw[s] * v;
        }
        g_QRY[(size_t)bq * CK + k] = qacc;
        #pragma unroll
        for (int s = 0; s < 4; s++) {
            int y = ky[s] + di, x = kx[s] + dj;
            float v = ((unsigned)y < 64u && (unsigned)x < 64u) ? fc[y * 64 + x] : 0.f;
            g_INP[((size_t)(bq * 4 + s)) * KINP + k] = v;
        }
    }
    if (tid < 4) {
        int s = tid;
        size_t base = ((size_t)(bq * 4 + s)) * KINP;
        g_INP[base + 576] = kr0[s];
        g_INP[base + 577] = kr1[s];
        g_INP[base + 578] = s0 * 64.0f;
        g_INP[base + 579] = s1 * 64.0f;
        g_INP[base + 580] = 0.f;
        g_INP[base + 581] = 0.f;
        g_INP[base + 582] = 0.f;
        g_INP[base + 583] = 0.f;
    }
}

// ---------------- SGEMM 128x128x8, 256 threads, 8x8 per thread -------------
// A [M,K] row-major (lda=K), B [K,N] row-major, C [M,N] row-major.
// Requires: K % 8 == 0, M % 128 == 0. N-edge guarded.
// EPI: 0 = relu(acc+bias), 1 = (acc+bias)*mul[m*ldmul+n], 2 = acc+bias
template<int EPI>
__global__ __launch_bounds__(256) void sgemm_kernel(
    const float* __restrict__ A, const float* __restrict__ Bm,
    float* __restrict__ Cm, const float* __restrict__ bias,
    const float* __restrict__ mul, int ldmul,
    int M, int N, int K)
{
    __shared__ float As[8][128];
    __shared__ float Bs[8][128];

    const int tid = threadIdx.x;
    const int bm = blockIdx.y * 128;
    const int bn = blockIdx.x * 128;
    const int tx = tid & 15;       // 16 thread-cols * TN=8
    const int ty = tid >> 4;       // 16 thread-rows * TM=8

    const int arow = tid >> 1, acol = (tid & 1) * 4;
    const int brow = tid >> 5, bcol = (tid & 31) * 4;

    float acc[8][8];
    #pragma unroll
    for (int i = 0; i < 8; i++)
        #pragma unroll
        for (int j = 0; j < 8; j++) acc[i][j] = 0.f;

    const float* Aptr = A + (size_t)(bm + arow) * K + acol;

    for (int k0 = 0; k0 < K; k0 += 8) {
        float4 av = *(const float4*)(Aptr + k0);
        As[acol + 0][arow] = av.x;
        As[acol + 1][arow] = av.y;
        As[acol + 2][arow] = av.z;
        As[acol + 3][arow] = av.w;

        int gn = bn + bcol;
        float4 bv;
        if (gn + 3 < N) {
            bv = *(const float4*)(Bm + (size_t)(k0 + brow) * N + gn);
        } else {
            bv.x = (gn + 0 < N) ? Bm[(size_t)(k0 + brow) * N + gn + 0] : 0.f;
            bv.y = (gn + 1 < N) ? Bm[(size_t)(k0 + brow) * N + gn + 1] : 0.f;
            bv.z = (gn + 2 < N) ? Bm[(size_t)(k0 + brow) * N + gn + 2] : 0.f;
            bv.w = (gn + 3 < N) ? Bm[(size_t)(k0 + brow) * N + gn + 3] : 0.f;
        }
        *(float4*)&Bs[brow][bcol] = bv;

        __syncthreads();

        #pragma unroll
        for (int kk = 0; kk < 8; kk++) {
            float4 a0 = *(const float4*)&As[kk][ty * 8];
            float4 a1 = *(const float4*)&As[kk][ty * 8 + 4];
            float4 b0 = *(const float4*)&Bs[kk][tx * 8];
            float4 b1 = *(const float4*)&Bs[kk][tx * 8 + 4];
            float ar[8] = {a0.x, a0.y, a0.z, a0.w, a1.x, a1.y, a1.z, a1.w};
            float br[8] = {b0.x, b0.y, b0.z, b0.w, b1.x, b1.y, b1.z, b1.w};
            #pragma unroll
            for (int i = 0; i < 8; i++)
                #pragma unroll
                for (int j = 0; j < 8; j++)
                    acc[i][j] += ar[i] * br[j];
        }
        __syncthreads();
    }

    #pragma unroll
    for (int i = 0; i < 8; i++) {
        int gm = bm + ty * 8 + i;
        #pragma unroll
        for (int j = 0; j < 8; j++) {
            int gn = bn + tx * 8 + j;
            if (gn < N) {
                float v = acc[i][j] + bias[gn];
                if (EPI == 0) v = fmaxf(v, 0.f);
                if (EPI == 1) v = v * mul[(size_t)gm * ldmul + gn];
                Cm[(size_t)gm * N + gn] = v;
            }
        }
    }
}

// ---------------- attention: dot, softmax(4), weighted sum -----------------
__global__ __launch_bounds__(192) void attn_kernel() {
    const int bq = blockIdx.x;
    const int tid = threadIdx.x;
    const float* qrow = g_QRY + (size_t)bq * CK;
    const size_t r0 = (size_t)bq * 4 * CK;

    float p[4] = {0.f, 0.f, 0.f, 0.f};
    for (int c = tid; c < CK; c += 192) {
        float qv = qrow[c];
        #pragma unroll
        for (int s = 0; s < 4; s++)
            p[s] += qv * g_PK[r0 + (size_t)s * CK + c];
    }
    #pragma unroll
    for (int off = 16; off; off >>= 1)
        #pragma unroll
        for (int s = 0; s < 4; s++)
            p[s] += __shfl_down_sync(0xffffffffu, p[s], off);

    __shared__ float red[4][6];
    __shared__ float wsm[4];
    int warp = tid >> 5, lane = tid & 31;
    if (lane == 0)
        #pragma unroll
        for (int s = 0; s < 4; s++) red[s][warp] = p[s];
    __syncthreads();
    if (tid == 0) {
        float attn[4];
        #pragma unroll
        for (int s = 0; s < 4; s++)
            attn[s] = red[s][0] + red[s][1] + red[s][2] + red[s][3] + red[s][4] + red[s][5];
        float m = fmaxf(fmaxf(attn[0], attn[1]), fmaxf(attn[2], attn[3]));
        float e[4], t = 0.f;
        #pragma unroll
        for (int s = 0; s < 4; s++) { e[s] = expf(attn[s] - m); t += e[s]; }
        float inv = 1.0f / t;
        #pragma unroll
        for (int s = 0; s < 4; s++) wsm[s] = e[s] * inv;
    }
    __syncthreads();
    float w0 = wsm[0], w1 = wsm[1], w2 = wsm[2], w3 = wsm[3];
    for (int c = tid; c < CK; c += 192) {
        float x = w0 * g_PV[r0 + 0 * CK + c]
                + w1 * g_PV[r0 + 1 * CK + c]
                + w2 * g_PV[r0 + 2 * CK + c]
                + w3 * g_PV[r0 + 3 * CK + c];
        g_X[(size_t)bq * CK + c] = x;
    }
}

// ---------------- final projection: [8192,256] @ [256,3] + bias ------------
__global__ __launch_bounds__(128) void outproj_kernel(
    const float* __restrict__ qW2, const float* __restrict__ qb2,
    float* __restrict__ out)
{
    int warp = threadIdx.x >> 5, lane = threadIdx.x & 31;
    int row = blockIdx.x * 4 + warp;
    const float* h = g_Hq + (size_t)row * HID;
    float a0 = 0.f, a1 = 0.f, a2 = 0.f;
    #pragma unroll
    for (int i = 0; i < 8; i++) {
        int k = i * 32 + lane;
        float a = h[k];
        a0 += a * qW2[k * 3 + 0];
        a1 += a * qW2[k * 3 + 1];
        a2 += a * qW2[k * 3 + 2];
    }
    #pragma unroll
    for (int off = 16; off; off >>= 1) {
        a0 += __shfl_down_sync(0xffffffffu, a0, off);
        a1 += __shfl_down_sync(0xffffffffu, a1, off);
        a2 += __shfl_down_sync(0xffffffffu, a2, off);
    }
    if (lane == 0) {
        out[row * 3 + 0] = a0 + qb2[0];
        out[row * 3 + 1] = a1 + qb2[1];
        out[row * 3 + 2] = a2 + qb2[2];
    }
}

// ---------------- launch ---------------------------------------------------
extern "C" void kernel_launch(void* const* d_in, const int* in_sizes, int n_in,
                              void* d_out, int out_size) {
    const float* feature = (const float*)d_in[0];
    const float* coord   = (const float*)d_in[1];
    const float* scale   = (const float*)d_in[2];
    const float* kW1 = (const float*)d_in[3];
    const float* kb1 = (const float*)d_in[4];
    const float* kW2 = (const float*)d_in[5];
    const float* kb2 = (const float*)d_in[6];
    const float* vW1 = (const float*)d_in[7];
    const float* vb1 = (const float*)d_in[8];
    const float* vW2 = (const float*)d_in[9];
    const float* vb2 = (const float*)d_in[10];
    const float* qW1 = (const float*)d_in[11];
    const float* qb1 = (const float*)d_in[12];
    const float* qW2 = (const float*)d_in[13];
    const float* qb2 = (const float*)d_in[14];
    float* out = (float*)d_out;

    float *pINP, *pQRY, *pHk, *pHv, *pPK, *pPV, *pX, *pHq, *pkW1p, *pvW1p;
    cudaGetSymbolAddress((void**)&pINP,  g_INP);
    cudaGetSymbolAddress((void**)&pQRY,  g_QRY);
    cudaGetSymbolAddress((void**)&pHk,   g_Hk);
    cudaGetSymbolAddress((void**)&pHv,   g_Hv);
    cudaGetSymbolAddress((void**)&pPK,   g_PK);
    cudaGetSymbolAddress((void**)&pPV,   g_PV);
    cudaGetSymbolAddress((void**)&pX,    g_X);
    cudaGetSymbolAddress((void**)&pHq,   g_Hq);
    cudaGetSymbolAddress((void**)&pkW1p, g_kW1p);
    cudaGetSymbolAddress((void**)&pvW1p, g_vW1p);

    // 0) pad layer-1 weights to K=584
    pad_w1_kernel<<<(KINP * HID + 255) / 256, 256>>>(kW1, vW1);

    // 1) gather/setup
    setup_kernel<<<NROW, 128>>>(feature, coord, scale);

    // 2) layer-1 MLPs:  H = relu(INP @ W1p + b1)    [32768 x 256]
    {
        dim3 grid(HID / 128, NROW4 / 128);
        sgemm_kernel<0><<<grid, 256>>>(pINP, pkW1p, pHk, kb1, nullptr, 0, NROW4, HID, KINP);
        sgemm_kernel<0><<<grid, 256>>>(pINP, pvW1p, pHv, vb1, nullptr, 0, NROW4, HID, KINP);
    }

    // 3) layer-2 MLPs:  P = kv * (H @ W2 + b2)      [32768 x 576]
    {
        dim3 grid((CK + 127) / 128, NROW4 / 128);
        sgemm_kernel<1><<<grid, 256>>>(pHk, kW2, pPK, kb2, pINP, KINP, NROW4, CK, HID);
        sgemm_kernel<1><<<grid, 256>>>(pHv, vW2, pPV, vb2, pINP, KINP, NROW4, CK, HID);
    }

    // 4) attention + softmax + weighted sum -> X   [8192 x 576]
    attn_kernel<<<NROW, 192>>>();

    // 5) query MLP layer 1: Hq = relu(X @ qW1 + qb1)  [8192 x 256]
    {
        dim3 grid(HID / 128, NROW / 128);
        sgemm_kernel<0><<<grid, 256>>>(pX, qW1, pHq, qb1, nullptr, 0, NROW, HID, CK);
    }

    // 6) output projection  [8192 x 3]
    outproj_kernel<<<NROW / 4, 128>>>(qW2, qb2, out);
}

// round 4
// speedup vs baseline: 2.9125x; 2.9125x over previous
#include <cuda_runtime.h>
#include <cuda_bf16.h>
#include <math.h>
#include <stdint.h>

// Problem constants
#define BB 2
#define QQ 4096
#define CC 64
#define HH 64
#define WW 64
#define CK 576          // C*9
#define KIN 580         // CK + 4
#define KINP 608        // padded to multiple of 32
#define HID 256
#define NROW (BB*QQ)        // 8192
#define NROW4 (BB*QQ*4)     // 32768

// ---------------- scratch (device globals; no allocation) ----------------
__device__ float g_INP[NROW4 * KINP];     // [32768, 608] tf32-rounded
__device__ float g_QRY[NROW * CK];        // [8192, 576] fp32
__device__ float g_Hk [NROW4 * HID];      // tf32-rounded (EPI0)
__device__ float g_Hv [NROW4 * HID];
__device__ float g_PK [NROW4 * CK];       // fp32
__device__ float g_PV [NROW4 * CK];
__device__ float g_X  [NROW * CK];        // tf32-rounded
__device__ float g_Hq [NROW * HID];
// transposed weights, [N, K] K-major (tf32-rounded)
__device__ float g_kW1t[HID * KINP];
__device__ float g_vW1t[HID * KINP];
__device__ float g_kW2t[CK * HID];
__device__ float g_vW2t[CK * HID];
__device__ float g_qW1t[HID * CK];

__device__ __forceinline__ float tf32r(float x) {
    uint32_t y;
    asm("cvt.rna.tf32.f32 %0, %1;" : "=r"(y) : "f"(x));
    return __uint_as_float(y);
}
__device__ __forceinline__ uint32_t s2u(const void* p) {
    uint32_t a;
    asm("{ .reg .u64 t; cvta.to.shared.u64 t, %1; cvt.u32.u64 %0, t; }" : "=r"(a) : "l"(p));
    return a;
}

// ---------------- weight transpose / pad / tf32 round ----------------------
__global__ void prep_weights(const float* __restrict__ kW1, const float* __restrict__ vW1,
                             const float* __restrict__ kW2, const float* __restrict__ vW2,
                             const float* __restrict__ qW1) {
    int i = blockIdx.x * 256 + threadIdx.x;
    if (i < HID * KINP) {           // [256, 608] from [580, 256]
        int n = i / KINP, k = i - n * KINP;
        float a = 0.f, b = 0.f;
        if (k < KIN) { a = kW1[k * HID + n]; b = vW1[k * HID + n]; }
        g_kW1t[i] = tf32r(a); g_vW1t[i] = tf32r(b);
    }
    if (i < CK * HID) {             // [576, 256] from [256, 576]
        int n = i / HID, k = i - n * HID;
        g_kW2t[i] = tf32r(kW2[k * CK + n]);
        g_vW2t[i] = tf32r(vW2[k * CK + n]);
    }
    if (i < HID * CK) {             // [256, 576] from [576, 256]
        int n = i / CK, k = i - n * CK;
        g_qW1t[i] = tf32r(qW1[k * HID + n]);
    }
}

// ---------------- setup: gather unfold samples, build INP + query ----------
__device__ __forceinline__ int nearest_idx(float c) {
    float f = ((c + 1.0f) * 64.0f - 1.0f) * 0.5f + 0.5f;
    int i = (int)floorf(f);
    return i < 0 ? 0 : (i > 63 ? 63 : i);
}

__global__ __launch_bounds__(128) void setup_kernel(
    const float* __restrict__ feature, const float* __restrict__ coord,
    const float* __restrict__ scale) {
    const int bq = blockIdx.x;
    const int b  = bq >> 12;
    const int tid = threadIdx.x;

    const float cy = coord[bq * 2 + 0];
    const float cx = coord[bq * 2 + 1];
    const float s0 = scale[bq * 2 + 0];
    const float s1 = scale[bq * 2 + 1];
    const float lo = -1.0f + 1e-6f, hi = 1.0f - 1e-6f;

    int   qy[4], qx[4];
    float area[4];
    const float rx = 1.0f / 64.0f, ry = 1.0f / 64.0f;
    #pragma unroll
    for (int s = 0; s < 4; s++) {
        float vx = (s >= 2) ? 1.0f : -1.0f;
        float vy = (s & 1)  ? 1.0f : -1.0f;
        float c0 = fminf(fmaxf(cy + vx * rx + 1e-6f, lo), hi);
        float c1 = fminf(fmaxf(cx + vy * ry + 1e-6f, lo), hi);
        int iy = nearest_idx(c0), ix = nearest_idx(c1);
        qy[s] = iy; qx[s] = ix;
        float qc0 = -1.0f + (2.0f * iy + 1.0f) / 64.0f;
        float qc1 = -1.0f + (2.0f * ix + 1.0f) / 64.0f;
        area[s] = fabsf((cy - qc0) * 64.0f * (cx - qc1) * 64.0f) + 1e-9f;
    }
    float tot = area[0] + area[1] + area[2] + area[3];
    float qw[4];
    #pragma unroll
    for (int s = 0; s < 4; s++) qw[s] = area[3 - s] / tot;

    const float sc00 = scale[(b * QQ) * 2 + 0];
    const float sc01 = scale[(b * QQ) * 2 + 1];
    const float invtx = (1.0f - sc00) / 63.0f;
    const float invty = (1.0f - sc01) / 63.0f;
    int   ky[4], kx[4];
    float kr0[4], kr1[4];
    #pragma unroll
    for (int s = 0; s < 4; s++) {
        float vx = (s >= 2) ? 1.0f : -1.0f;
        float vy = (s & 1)  ? 1.0f : -1.0f;
        float c0 = fminf(fmaxf(cy + vx * invtx + 1e-6f, lo), hi);
        float c1 = fminf(fmaxf(cx + vy * invty + 1e-6f, lo), hi);
        int iy = nearest_idx(c0), ix = nearest_idx(c1);
        ky[s] = iy; kx[s] = ix;
        float qc0 = -1.0f + (2.0f * iy + 1.0f) / 64.0f;
        float qc1 = -1.0f + (2.0f * ix + 1.0f) / 64.0f;
        kr0[s] = (cy - qc0) * 64.0f;
        kr1[s] = (cx - qc1) * 64.0f;
    }

    const float* fb = feature + (size_t)b * CC * HH * WW;
    for (int k = tid; k < CK; k += 128) {
        int c = k / 9, p = k - c * 9;
        int di = p / 3 - 1, dj = p - (p / 3) * 3 - 1;
        const float* fc = fb + (size_t)c * (HH * WW);
        float qacc = 0.f;
        #pragma unroll
        for (int s = 0; s < 4; s++) {
            int y = qy[s] + di, x = qx[s] + dj;
            float v = ((unsigned)y < 64u && (unsigned)x < 64u) ? fc[y * 64 + x] : 0.f;
            qacc += qw[s] * v;
        }
        g_QRY[(size_t)bq * CK + k] = qacc;
        #pragma unroll
        for (int s = 0; s < 4; s++) {
            int y = ky[s] + di, x = kx[s] + dj;
            float v = ((unsigned)y < 64u && (unsigned)x < 64u) ? fc[y * 64 + x] : 0.f;
            g_INP[((size_t)(bq * 4 + s)) * KINP + k] = tf32r(v);
        }
    }
    {   // cols 576..607: rel(2), scale(2), zeros. 128 thr = 4 shifts x 32 cols.
        int s = tid >> 5, cc = tid & 31;
        float v = 0.f;
        if (cc == 0) v = kr0[s];
        else if (cc == 1) v = kr1[s];
        else if (cc == 2) v = s0 * 64.0f;
        else if (cc == 3) v = s1 * 64.0f;
        g_INP[((size_t)(bq * 4 + s)) * KINP + 576 + cc] = tf32r(v);
    }
}

// ---------------- mma.sync tf32 GEMM ---------------------------------------
// C[M,N] = A[M,K] @ B[N,K]^T.  BM=128, BN=128, BK=32.
// K%32==0, M%128==0; N-edge guarded (B rows + C cols).
// EPI 0: tf32r(relu(acc+bias)).  EPI 1: (acc+bias)*mul[gm*ldmul+gn].
#define PS 40                      // smem row stride (floats)
#define ABUF (128*PS)              // 5120 floats per buffer

__device__ __forceinline__ void cp16(uint32_t dst, const float* src) {
    asm volatile("cp.async.cg.shared.global [%0], [%1], 16;" :: "r"(dst), "l"(src) : "memory");
}
__device__ __forceinline__ void cp16p(uint32_t dst, const float* src, int sz) {
    asm volatile("cp.async.cg.shared.global [%0], [%1], 16, %2;" :: "r"(dst), "l"(src), "r"(sz) : "memory");
}

template<int EPI>
__global__ __launch_bounds__(256, 2) void mma_gemm(
    const float* __restrict__ A, const float* __restrict__ B,
    float* __restrict__ C, const float* __restrict__ bias,
    const float* __restrict__ mul, int ldmul, int K, int N) {
    extern __shared__ float sm[];
    const int tid = threadIdx.x;
    const int lane = tid & 31, wid = tid >> 5;
    const int g = lane >> 2, tg = lane & 3;
    const int wm = (wid & 3) * 32, wn = (wid >> 2) * 64;
    const int bm = blockIdx.y * 128, bn = blockIdx.x * 128;
    const int S = K >> 5;
    const uint32_t sA = s2u(sm);
    const uint32_t sB = sA + 2 * ABUF * 4;

    const float* Ab = A + (size_t)bm * K;
    const float* Bb = B + (size_t)bn * K;

    float acc[2][8][4];
    #pragma unroll
    for (int mt = 0; mt < 2; mt++)
        #pragma unroll
        for (int nt = 0; nt < 8; nt++)
            #pragma unroll
            for (int j = 0; j < 4; j++) acc[mt][nt][j] = 0.f;

    // prologue: stage 0
    #pragma unroll
    for (int r = 0; r < 4; r++) {
        int i = tid + r * 256;
        int row = i >> 3, c4 = (i & 7) * 4;
        cp16(sA + (uint32_t)(row * PS + c4) * 4, Ab + (size_t)row * K + c4);
        int ok = (bn + row < N) ? 16 : 0;
        cp16p(sB + (uint32_t)(row * PS + c4) * 4, ok ? (Bb + (size_t)row * K + c4) : B, ok);
    }
    asm volatile("cp.async.commit_group;" ::: "memory");

    for (int s = 0; s < S; s++) {
        asm volatile("cp.async.wait_group 0;" ::: "memory");
        __syncthreads();

        if (s + 1 < S) {
            int k0 = (s + 1) * 32;
            uint32_t dA = sA + ((s + 1) & 1) * ABUF * 4;
            uint32_t dB = sB + ((s + 1) & 1) * ABUF * 4;
            #pragma unroll
            for (int r = 0; r < 4; r++) {
                int i = tid + r * 256;
                int row = i >> 3, c4 = (i & 7) * 4;
                cp16(dA + (uint32_t)(row * PS + c4) * 4, Ab + (size_t)row * K + k0 + c4);
                int ok = (bn + row < N) ? 16 : 0;
                cp16p(dB + (uint32_t)(row * PS + c4) * 4,
                      ok ? (Bb + (size_t)row * K + k0 + c4) : B, ok);
            }
            asm volatile("cp.async.commit_group;" ::: "memory");
        }

        const float* As = sm + (s & 1) * ABUF;
        const float* Bs = sm + 2 * ABUF + (s & 1) * ABUF;

        #pragma unroll
        for (int ks = 0; ks < 4; ks++) {
            int kb = ks * 8;
            uint32_t a[2][4], bfr[8][2];
            #pragma unroll
            for (int mt = 0; mt < 2; mt++) {
                int m0 = wm + mt * 16;
                a[mt][0] = __float_as_uint(As[(m0 + g)     * PS + kb + tg]);
                a[mt][1] = __float_as_uint(As[(m0 + g + 8) * PS + kb + tg]);
                a[mt][2] = __float_as_uint(As[(m0 + g)     * PS + kb + tg + 4]);
                a[mt][3] = __float_as_uint(As[(m0 + g + 8) * PS + kb + tg + 4]);
            }
            #pragma unroll
            for (int nt = 0; nt < 8; nt++) {
                int n0 = wn + nt * 8 + g;
                bfr[nt][0] = __float_as_uint(Bs[n0 * PS + kb + tg]);
                bfr[nt][1] = __float_as_uint(Bs[n0 * PS + kb + tg + 4]);
            }
            #pragma unroll
            for (int mt = 0; mt < 2; mt++)
                #pragma unroll
                for (int nt = 0; nt < 8; nt++)
                    asm volatile(
                        "mma.sync.aligned.m16n8k8.row.col.f32.tf32.tf32.f32 "
                        "{%0,%1,%2,%3}, {%4,%5,%6,%7}, {%8,%9}, {%0,%1,%2,%3};"
                        : "+f"(acc[mt][nt][0]), "+f"(acc[mt][nt][1]),
                          "+f"(acc[mt][nt][2]), "+f"(acc[mt][nt][3])
                        : "r"(a[mt][0]), "r"(a[mt][1]), "r"(a[mt][2]), "r"(a[mt][3]),
                          "r"(bfr[nt][0]), "r"(bfr[nt][1]));
        }
        __syncthreads();
    }

    // epilogue
    #pragma unroll
    for (int mt = 0; mt < 2; mt++) {
        int gm0 = bm + wm + mt * 16 + g;
        #pragma unroll
        for (int nt = 0; nt < 8; nt++) {
            int gn = bn + wn + nt * 8 + 2 * tg;
            if (gn < N) {
                float b0 = bias[gn], b1 = bias[gn + 1];
                float v0 = acc[mt][nt][0] + b0;
                float v1 = acc[mt][nt][1] + b1;
                float v2 = acc[mt][nt][2] + b0;
                float v3 = acc[mt][nt][3] + b1;
                if (EPI == 0) {
                    v0 = tf32r(fmaxf(v0, 0.f)); v1 = tf32r(fmaxf(v1, 0.f));
                    v2 = tf32r(fmaxf(v2, 0.f)); v3 = tf32r(fmaxf(v3, 0.f));
                } else {
                    float2 m0v = *(const float2*)(mul + (size_t)gm0 * ldmul + gn);
                    float2 m1v = *(const float2*)(mul + (size_t)(gm0 + 8) * ldmul + gn);
                    v0 *= m0v.x; v1 *= m0v.y; v2 *= m1v.x; v3 *= m1v.y;
                }
                float2 o0 = {v0, v1}, o1 = {v2, v3};
                *(float2*)(C + (size_t)gm0 * N + gn) = o0;
                *(float2*)(C + (size_t)(gm0 + 8) * N + gn) = o1;
            }
        }
    }
}

// ---------------- attention: dot, softmax(4), weighted sum -----------------
__global__ __launch_bounds__(192) void attn_kernel() {
    const int bq = blockIdx.x;
    const int tid = threadIdx.x;
    const float* qrow = g_QRY + (size_t)bq * CK;
    const size_t r0 = (size_t)bq * 4 * CK;

    float p[4] = {0.f, 0.f, 0.f, 0.f};
    for (int c = tid; c < CK; c += 192) {
        float qv = qrow[c];
        #pragma unroll
        for (int s = 0; s < 4; s++)
            p[s] += qv * g_PK[r0 + (size_t)s * CK + c];
    }
    #pragma unroll
    for (int off = 16; off; off >>= 1)
        #pragma unroll
        for (int s = 0; s < 4; s++)
            p[s] += __shfl_down_sync(0xffffffffu, p[s], off);

    __shared__ float red[4][6];
    __shared__ float wsm[4];
    int warp = tid >> 5, lane = tid & 31;
    if (lane == 0)
        #pragma unroll
        for (int s = 0; s < 4; s++) red[s][warp] = p[s];
    __syncthreads();
    if (tid == 0) {
        float attn[4];
        #pragma unroll
        for (int s = 0; s < 4; s++)
            attn[s] = red[s][0] + red[s][1] + red[s][2] + red[s][3] + red[s][4] + red[s][5];
        float m = fmaxf(fmaxf(attn[0], attn[1]), fmaxf(attn[2], attn[3]));
        float e[4], t = 0.f;
        #pragma unroll
        for (int s = 0; s < 4; s++) { e[s] = expf(attn[s] - m); t += e[s]; }
        float inv = 1.0f / t;
        #pragma unroll
        for (int s = 0; s < 4; s++) wsm[s] = e[s] * inv;
    }
    __syncthreads();
    float w0 = wsm[0], w1 = wsm[1], w2 = wsm[2], w3 = wsm[3];
    for (int c = tid; c < CK; c += 192) {
        float x = w0 * g_PV[r0 + 0 * CK + c]
                + w1 * g_PV[r0 + 1 * CK + c]
                + w2 * g_PV[r0 + 2 * CK + c]
                + w3 * g_PV[r0 + 3 * CK + c];
        g_X[(size_t)bq * CK + c] = tf32r(x);
    }
}

// ---------------- final projection: [8192,256] @ [256,3] + bias ------------
__global__ __launch_bounds__(128) void outproj_kernel(
    const float* __restrict__ qW2, const float* __restrict__ qb2,
    float* __restrict__ out) {
    int warp = threadIdx.x >> 5, lane = threadIdx.x & 31;
    int row = blockIdx.x * 4 + warp;
    const float* h = g_Hq + (size_t)row * HID;
    float a0 = 0.f, a1 = 0.f, a2 = 0.f;
    #pragma unroll
    for (int i = 0; i < 8; i++) {
        int k = i * 32 + lane;
        float a = h[k];
        a0 += a * qW2[k * 3 + 0];
        a1 += a * qW2[k * 3 + 1];
        a2 += a * qW2[k * 3 + 2];
    }
    #pragma unroll
    for (int off = 16; off; off >>= 1) {
        a0 += __shfl_down_sync(0xffffffffu, a0, off);
        a1 += __shfl_down_sync(0xffffffffu, a1, off);
        a2 += __shfl_down_sync(0xffffffffu, a2, off);
    }
    if (lane == 0) {
        out[row * 3 + 0] = a0 + qb2[0];
        out[row * 3 + 1] = a1 + qb2[1];
        out[row * 3 + 2] = a2 + qb2[2];
    }
}

// ---------------- launch ---------------------------------------------------
extern "C" void kernel_launch(void* const* d_in, const int* in_sizes, int n_in,
                              void* d_out, int out_size) {
    const float* feature = (const float*)d_in[0];
    const float* coord   = (const float*)d_in[1];
    const float* scale   = (const float*)d_in[2];
    const float* kW1 = (const float*)d_in[3];
    const float* kb1 = (const float*)d_in[4];
    const float* kW2 = (const float*)d_in[5];
    const float* kb2 = (const float*)d_in[6];
    const float* vW1 = (const float*)d_in[7];
    const float* vb1 = (const float*)d_in[8];
    const float* vW2 = (const float*)d_in[9];
    const float* vb2 = (const float*)d_in[10];
    const float* qW1 = (const float*)d_in[11];
    const float* qb1 = (const float*)d_in[12];
    const float* qW2 = (const float*)d_in[13];
    const float* qb2 = (const float*)d_in[14];
    float* out = (float*)d_out;

    float *pINP, *pHk, *pHv, *pPK, *pPV, *pX, *pHq;
    float *pkW1t, *pvW1t, *pkW2t, *pvW2t, *pqW1t;
    cudaGetSymbolAddress((void**)&pINP,  g_INP);
    cudaGetSymbolAddress((void**)&pHk,   g_Hk);
    cudaGetSymbolAddress((void**)&pHv,   g_Hv);
    cudaGetSymbolAddress((void**)&pPK,   g_PK);
    cudaGetSymbolAddress((void**)&pPV,   g_PV);
    cudaGetSymbolAddress((void**)&pX,    g_X);
    cudaGetSymbolAddress((void**)&pHq,   g_Hq);
    cudaGetSymbolAddress((void**)&pkW1t, g_kW1t);
    cudaGetSymbolAddress((void**)&pvW1t, g_vW1t);
    cudaGetSymbolAddress((void**)&pkW2t, g_kW2t);
    cudaGetSymbolAddress((void**)&pvW2t, g_vW2t);
    cudaGetSymbolAddress((void**)&pqW1t, g_qW1t);

    const int SMEM = 4 * ABUF * 4;   // 81920 bytes
    cudaFuncSetAttribute(mma_gemm<0>, cudaFuncAttributeMaxDynamicSharedMemorySize, SMEM);
    cudaFuncSetAttribute(mma_gemm<1>, cudaFuncAttributeMaxDynamicSharedMemorySize, SMEM);

    // 0) transpose/pad/round weights
    prep_weights<<<(HID * KINP + 255) / 256, 256>>>(kW1, vW1, kW2, vW2, qW1);

    // 1) gather/setup
    setup_kernel<<<NROW, 128>>>(feature, coord, scale);

    // 2) layer-1 MLPs:  H = tf32r(relu(INP @ W1t^T + b1))   [32768 x 256], K=608
    {
        dim3 grid(HID / 128, NROW4 / 128);
        mma_gemm<0><<<grid, 256, SMEM>>>(pINP, pkW1t, pHk, kb1, nullptr, 0, KINP, HID);
        mma_gemm<0><<<grid, 256, SMEM>>>(pINP, pvW1t, pHv, vb1, nullptr, 0, KINP, HID);
    }

    // 3) layer-2 MLPs:  P = kv * (H @ W2t^T + b2)    [32768 x 576], K=256
    {
        dim3 grid((CK + 127) / 128, NROW4 / 128);
        mma_gemm<1><<<grid, 256, SMEM>>>(pHk, pkW2t, pPK, kb2, pINP, KINP, HID, CK);
        mma_gemm<1><<<grid, 256, SMEM>>>(pHv, pvW2t, pPV, vb2, pINP, KINP, HID, CK);
    }

    // 4) attention + softmax + weighted sum -> X     [8192 x 576]
    attn_kernel<<<NROW, 192>>>();

    // 5) query MLP layer 1: Hq = relu(X @ qW1t^T + qb1)  [8192 x 256], K=576
    {
        dim3 grid(HID / 128, NROW / 128);
        mma_gemm<0><<<grid, 256, SMEM>>>(pX, pqW1t, pHq, qb1, nullptr, 0, CK, HID);
    }

    // 6) output projection  [8192 x 3]
    outproj_kernel<<<NROW / 4, 128>>>(qW2, qb2, out);
}

// round 5
// speedup vs baseline: 3.2413x; 1.1129x over previous
#include <cuda_runtime.h>
#include <cuda_bf16.h>
#include <math.h>
#include <stdint.h>

// Problem constants
#define BB 2
#define QQ 4096
#define CC 64
#define HH 64
#define WW 64
#define CK 576          // C*9
#define KIN 580         // CK + 4
#define KINP 608        // padded to multiple of 32
#define HID 256
#define NROW (BB*QQ)        // 8192
#define NROW4 (BB*QQ*4)     // 32768

// ---------------- scratch (device globals; no allocation) ----------------
__device__ float g_INP[NROW4 * KINP];     // [32768, 608] tf32-rounded
__device__ float g_QRY[NROW * CK];        // [8192, 576] fp32
__device__ float g_H  [NROW4 * 512];      // [32768, 512]: cols 0..255 Hk, 256..511 Hv
__device__ float g_PK [NROW4 * CK];       // fp32
__device__ float g_PV [NROW4 * CK];
__device__ float g_X  [NROW * CK];        // tf32-rounded
__device__ float g_Hq [NROW * HID];
// weights (tf32-rounded), [N, K] K-major
__device__ float g_W1t [512 * KINP];      // kW1t rows 0..255, vW1t rows 256..511
__device__ float g_b1  [512];
__device__ float g_kW2t[CK * HID];
__device__ float g_vW2t[CK * HID];
__device__ float g_qW1t[HID * CK];

__device__ __forceinline__ float tf32r(float x) {
    uint32_t y;
    asm("cvt.rna.tf32.f32 %0, %1;" : "=r"(y) : "f"(x));
    return __uint_as_float(y);
}
__device__ __forceinline__ uint32_t s2u(const void* p) {
    uint32_t a;
    asm("{ .reg .u64 t; cvta.to.shared.u64 t, %1; cvt.u32.u64 %0, t; }" : "=r"(a) : "l"(p));
    return a;
}

// ---------------- weight transpose / pad / tf32 round ----------------------
__global__ void prep_weights(const float* __restrict__ kW1, const float* __restrict__ vW1,
                             const float* __restrict__ kW2, const float* __restrict__ vW2,
                             const float* __restrict__ qW1,
                             const float* __restrict__ kb1, const float* __restrict__ vb1) {
    int i = blockIdx.x * 256 + threadIdx.x;
    if (i < 512 * KINP) {           // fused W1: [512, 608]
        int n = i / KINP, k = i - n * KINP;
        float v = 0.f;
        if (k < KIN) v = (n < HID) ? kW1[k * HID + n] : vW1[k * HID + (n - HID)];
        g_W1t[i] = tf32r(v);
    }
    if (i < CK * HID) {             // [576, 256] from [256, 576]
        int n = i / HID, k = i - n * HID;
        g_kW2t[i] = tf32r(kW2[k * CK + n]);
        g_vW2t[i] = tf32r(vW2[k * CK + n]);
    }
    if (i < HID * CK) {             // [256, 576] from [576, 256]
        int n = i / CK, k = i - n * CK;
        g_qW1t[i] = tf32r(qW1[k * HID + n]);
    }
    if (i < 512)
        g_b1[i] = (i < HID) ? kb1[i] : vb1[i - HID];
}

// ---------------- setup: gather unfold samples, build INP + query ----------
__device__ __forceinline__ int nearest_idx(float c) {
    float f = ((c + 1.0f) * 64.0f - 1.0f) * 0.5f + 0.5f;
    int i = (int)floorf(f);
    return i < 0 ? 0 : (i > 63 ? 63 : i);
}

__global__ __launch_bounds__(128) void setup_kernel(
    const float* __restrict__ feature, const float* __restrict__ coord,
    const float* __restrict__ scale) {
    const int bq = blockIdx.x;
    const int b  = bq >> 12;
    const int tid = threadIdx.x;

    const float cy = coord[bq * 2 + 0];
    const float cx = coord[bq * 2 + 1];
    const float s0 = scale[bq * 2 + 0];
    const float s1 = scale[bq * 2 + 1];
    const float lo = -1.0f + 1e-6f, hi = 1.0f - 1e-6f;

    int   qy[4], qx[4];
    float area[4];
    const float rx = 1.0f / 64.0f, ry = 1.0f / 64.0f;
    #pragma unroll
    for (int s = 0; s < 4; s++) {
        float vx = (s >= 2) ? 1.0f : -1.0f;
        float vy = (s & 1)  ? 1.0f : -1.0f;
        float c0 = fminf(fmaxf(cy + vx * rx + 1e-6f, lo), hi);
        float c1 = fminf(fmaxf(cx + vy * ry + 1e-6f, lo), hi);
        int iy = nearest_idx(c0), ix = nearest_idx(c1);
        qy[s] = iy; qx[s] = ix;
        float qc0 = -1.0f + (2.0f * iy + 1.0f) / 64.0f;
        float qc1 = -1.0f + (2.0f * ix + 1.0f) / 64.0f;
        area[s] = fabsf((cy - qc0) * 64.0f * (cx - qc1) * 64.0f) + 1e-9f;
    }
    float tot = area[0] + area[1] + area[2] + area[3];
    float qw[4];
    #pragma unroll
    for (int s = 0; s < 4; s++) qw[s] = area[3 - s] / tot;

    const float sc00 = scale[(b * QQ) * 2 + 0];
    const float sc01 = scale[(b * QQ) * 2 + 1];
    const float invtx = (1.0f - sc00) / 63.0f;
    const float invty = (1.0f - sc01) / 63.0f;
    int   ky[4], kx[4];
    float kr0[4], kr1[4];
    #pragma unroll
    for (int s = 0; s < 4; s++) {
        float vx = (s >= 2) ? 1.0f : -1.0f;
        float vy = (s & 1)  ? 1.0f : -1.0f;
        float c0 = fminf(fmaxf(cy + vx * invtx + 1e-6f, lo), hi);
        float c1 = fminf(fmaxf(cx + vy * invty + 1e-6f, lo), hi);
        int iy = nearest_idx(c0), ix = nearest_idx(c1);
        ky[s] = iy; kx[s] = ix;
        float qc0 = -1.0f + (2.0f * iy + 1.0f) / 64.0f;
        float qc1 = -1.0f + (2.0f * ix + 1.0f) / 64.0f;
        kr0[s] = (cy - qc0) * 64.0f;
        kr1[s] = (cx - qc1) * 64.0f;
    }

    const float* fb = feature + (size_t)b * CC * HH * WW;
    for (int k = tid; k < CK; k += 128) {
        int c = k / 9, p = k - c * 9;
        int di = p / 3 - 1, dj = p - (p / 3) * 3 - 1;
        const float* fc = fb + (size_t)c * (HH * WW);
        float qacc = 0.f;
        #pragma unroll
        for (int s = 0; s < 4; s++) {
            int y = qy[s] + di, x = qx[s] + dj;
            float v = ((unsigned)y < 64u && (unsigned)x < 64u) ? fc[y * 64 + x] : 0.f;
            qacc += qw[s] * v;
        }
        g_QRY[(size_t)bq * CK + k] = qacc;
        #pragma unroll
        for (int s = 0; s < 4; s++) {
            int y = ky[s] + di, x = kx[s] + dj;
            float v = ((unsigned)y < 64u && (unsigned)x < 64u) ? fc[y * 64 + x] : 0.f;
            g_INP[((size_t)(bq * 4 + s)) * KINP + k] = tf32r(v);
        }
    }
    {   // cols 576..607: rel(2), scale(2), zeros. 128 thr = 4 shifts x 32 cols.
        int s = tid >> 5, cc = tid & 31;
        float v = 0.f;
        if (cc == 0) v = kr0[s];
        else if (cc == 1) v = kr1[s];
        else if (cc == 2) v = s0 * 64.0f;
        else if (cc == 3) v = s1 * 64.0f;
        g_INP[((size_t)(bq * 4 + s)) * KINP + 576 + cc] = tf32r(v);
    }
}

// ---------------- mma.sync tf32 GEMM ---------------------------------------
// C[M,N] = A[M,K(lda)] @ B[N,K]^T.  BM=128, BN=128, BK=32, 3-stage cp.async.
// K%32==0, M%128==0; N-edge guarded.  PS=36: conflict-free fragment LDS.
// EPI 0: tf32r(relu(acc+bias)).  EPI 1: (acc+bias)*mul[gm*ldmul+gn].
#define PS 36
#define TILEF (128*PS)             // floats per operand buffer
#define STAGEF (2*TILEF)           // floats per stage (A+B)
#define SMEMB (3*STAGEF*4)         // 110592 bytes

__device__ __forceinline__ void cp16(uint32_t dst, const float* src) {
    asm volatile("cp.async.cg.shared.global [%0], [%1], 16;" :: "r"(dst), "l"(src) : "memory");
}
__device__ __forceinline__ void cp16p(uint32_t dst, const float* src, int sz) {
    asm volatile("cp.async.cg.shared.global [%0], [%1], 16, %2;" :: "r"(dst), "l"(src), "r"(sz) : "memory");
}

template<int EPI>
__global__ __launch_bounds__(256, 2) void mma_gemm(
    const float* __restrict__ A, int lda, const float* __restrict__ B,
    float* __restrict__ C, const float* __restrict__ bias,
    const float* __restrict__ mul, int ldmul, int K, int N) {
    extern __shared__ float sm[];
    const int tid = threadIdx.x;
    const int lane = tid & 31, wid = tid >> 5;
    const int g = lane >> 2, tg = lane & 3;
    const int wm = (wid & 3) * 32, wn = (wid >> 2) * 64;
    const int bm = blockIdx.y * 128, bn = blockIdx.x * 128;
    const int S = K >> 5;
    const uint32_t sbase = s2u(sm);

    const float* Ab = A + (size_t)bm * lda;
    const float* Bb = B + (size_t)bn * K;

    float acc[2][8][4];
    #pragma unroll
    for (int mt = 0; mt < 2; mt++)
        #pragma unroll
        for (int nt = 0; nt < 8; nt++)
            #pragma unroll
            for (int j = 0; j < 4; j++) acc[mt][nt][j] = 0.f;

    // stage loader: stage st gets K-block k0
    auto issue = [&](int st, int k0) {
        uint32_t sA = sbase + (uint32_t)(st * STAGEF) * 4;
        uint32_t sB = sA + (uint32_t)TILEF * 4;
        #pragma unroll
        for (int r = 0; r < 4; r++) {
            int i = tid + r * 256;
            int row = i >> 3, c4 = (i & 7) * 4;
            cp16(sA + (uint32_t)(row * PS + c4) * 4, Ab + (size_t)row * lda + k0 + c4);
            int ok = (bn + row < N) ? 16 : 0;
            cp16p(sB + (uint32_t)(row * PS + c4) * 4,
                  ok ? (Bb + (size_t)row * K + k0 + c4) : B, ok);
        }
        asm volatile("cp.async.commit_group;" ::: "memory");
    };

    issue(0, 0);
    issue(1, 32);

    for (int s = 0; s < S; s++) {
        asm volatile("cp.async.wait_group 1;" ::: "memory");
        __syncthreads();

        if (s + 2 < S) issue((s + 2) % 3, (s + 2) * 32);

        const float* As = sm + (s % 3) * STAGEF;
        const float* Bs = As + TILEF;

        #pragma unroll
        for (int ks = 0; ks < 4; ks++) {
            int kb = ks * 8;
            uint32_t a[2][4], bfr[8][2];
            #pragma unroll
            for (int mt = 0; mt < 2; mt++) {
                int m0 = wm + mt * 16;
                a[mt][0] = __float_as_uint(As[(m0 + g)     * PS + kb + tg]);
                a[mt][1] = __float_as_uint(As[(m0 + g + 8) * PS + kb + tg]);
                a[mt][2] = __float_as_uint(As[(m0 + g)     * PS + kb + tg + 4]);
                a[mt][3] = __float_as_uint(As[(m0 + g + 8) * PS + kb + tg + 4]);
            }
            #pragma unroll
            for (int nt = 0; nt < 8; nt++) {
                int n0 = wn + nt * 8 + g;
                bfr[nt][0] = __float_as_uint(Bs[n0 * PS + kb + tg]);
                bfr[nt][1] = __float_as_uint(Bs[n0 * PS + kb + tg + 4]);
            }
            #pragma unroll
            for (int mt = 0; mt < 2; mt++)
                #pragma unroll
                for (int nt = 0; nt < 8; nt++)
                    asm volatile(
                        "mma.sync.aligned.m16n8k8.row.col.f32.tf32.tf32.f32 "
                        "{%0,%1,%2,%3}, {%4,%5,%6,%7}, {%8,%9}, {%0,%1,%2,%3};"
                        : "+f"(acc[mt][nt][0]), "+f"(acc[mt][nt][1]),
                          "+f"(acc[mt][nt][2]), "+f"(acc[mt][nt][3])
                        : "r"(a[mt][0]), "r"(a[mt][1]), "r"(a[mt][2]), "r"(a[mt][3]),
                          "r"(bfr[nt][0]), "r"(bfr[nt][1]));
        }
        __syncthreads();
    }

    // epilogue
    #pragma unroll
    for (int mt = 0; mt < 2; mt++) {
        int gm0 = bm + wm + mt * 16 + g;
        #pragma unroll
        for (int nt = 0; nt < 8; nt++) {
            int gn = bn + wn + nt * 8 + 2 * tg;
            if (gn < N) {
                float b0 = bias[gn], b1 = bias[gn + 1];
                float v0 = acc[mt][nt][0] + b0;
                float v1 = acc[mt][nt][1] + b1;
                float v2 = acc[mt][nt][2] + b0;
                float v3 = acc[mt][nt][3] + b1;
                if (EPI == 0) {
                    v0 = tf32r(fmaxf(v0, 0.f)); v1 = tf32r(fmaxf(v1, 0.f));
                    v2 = tf32r(fmaxf(v2, 0.f)); v3 = tf32r(fmaxf(v3, 0.f));
                } else {
                    float2 m0v = *(const float2*)(mul + (size_t)gm0 * ldmul + gn);
                    float2 m1v = *(const float2*)(mul + (size_t)(gm0 + 8) * ldmul + gn);
                    v0 *= m0v.x; v1 *= m0v.y; v2 *= m1v.x; v3 *= m1v.y;
                }
                float2 o0 = {v0, v1}, o1 = {v2, v3};
                *(float2*)(C + (size_t)gm0 * N + gn) = o0;
                *(float2*)(C + (size_t)(gm0 + 8) * N + gn) = o1;
            }
        }
    }
}

// ---------------- attention: dot, softmax(4), weighted sum (float4) --------
__global__ __launch_bounds__(192) void attn_kernel() {
    const int bq = blockIdx.x;
    const int tid = threadIdx.x;
    const float4* q4  = (const float4*)(g_QRY + (size_t)bq * CK);
    const float4* pk4 = (const float4*)(g_PK + (size_t)bq * 4 * CK);
    const float4* pv4 = (const float4*)(g_PV + (size_t)bq * 4 * CK);

    float p[4] = {0.f, 0.f, 0.f, 0.f};
    if (tid < 144) {                       // CK/4 = 144
        float4 q = q4[tid];
        #pragma unroll
        for (int s = 0; s < 4; s++) {
            float4 k = pk4[s * 144 + tid];
            p[s] = q.x * k.x + q.y * k.y + q.z * k.z + q.w * k.w;
        }
    }
    #pragma unroll
    for (int off = 16; off; off >>= 1)
        #pragma unroll
        for (int s = 0; s < 4; s++)
            p[s] += __shfl_down_sync(0xffffffffu, p[s], off);

    __shared__ float red[4][6];
    __shared__ float wsm[4];
    int warp = tid >> 5, lane = tid & 31;
    if (lane == 0)
        #pragma unroll
        for (int s = 0; s < 4; s++) red[s][warp] = p[s];
    __syncthreads();
    if (tid == 0) {
        float attn[4];
        #pragma unroll
        for (int s = 0; s < 4; s++)
            attn[s] = red[s][0] + red[s][1] + red[s][2] + red[s][3] + red[s][4] + red[s][5];
        float m = fmaxf(fmaxf(attn[0], attn[1]), fmaxf(attn[2], attn[3]));
        float e[4], t = 0.f;
        #pragma unroll
        for (int s = 0; s < 4; s++) { e[s] = expf(attn[s] - m); t += e[s]; }
        float inv = 1.0f / t;
        #pragma unroll
        for (int s = 0; s < 4; s++) wsm[s] = e[s] * inv;
    }
    __syncthreads();
    if (tid < 144) {
        float w0 = wsm[0], w1 = wsm[1], w2 = wsm[2], w3 = wsm[3];
        float4 v0 = pv4[tid], v1 = pv4[144 + tid], v2 = pv4[288 + tid], v3 = pv4[432 + tid];
        float4 x;
        x.x = tf32r(w0 * v0.x + w1 * v1.x + w2 * v2.x + w3 * v3.x);
        x.y = tf32r(w0 * v0.y + w1 * v1.y + w2 * v2.y + w3 * v3.y);
        x.z = tf32r(w0 * v0.z + w1 * v1.z + w2 * v2.z + w3 * v3.z);
        x.w = tf32r(w0 * v0.w + w1 * v1.w + w2 * v2.w + w3 * v3.w);
        ((float4*)(g_X + (size_t)bq * CK))[tid] = x;
    }
}

// ---------------- final projection: [8192,256] @ [256,3] + bias ------------
__global__ __launch_bounds__(128) void outproj_kernel(
    const float* __restrict__ qW2, const float* __restrict__ qb2,
    float* __restrict__ out) {
    int warp = threadIdx.x >> 5, lane = threadIdx.x & 31;
    int row = blockIdx.x * 4 + warp;
    const float* h = g_Hq + (size_t)row * HID;
    float a0 = 0.f, a1 = 0.f, a2 = 0.f;
    #pragma unroll
    for (int i = 0; i < 8; i++) {
        int k = i * 32 + lane;
        float a = h[k];
        a0 += a * qW2[k * 3 + 0];
        a1 += a * qW2[k * 3 + 1];
        a2 += a * qW2[k * 3 + 2];
    }
    #pragma unroll
    for (int off = 16; off; off >>= 1) {
        a0 += __shfl_down_sync(0xffffffffu, a0, off);
        a1 += __shfl_down_sync(0xffffffffu, a1, off);
        a2 += __shfl_down_sync(0xffffffffu, a2, off);
    }
    if (lane == 0) {
        out[row * 3 + 0] = a0 + qb2[0];
        out[row * 3 + 1] = a1 + qb2[1];
        out[row * 3 + 2] = a2 + qb2[2];
    }
}

// ---------------- launch ---------------------------------------------------
extern "C" void kernel_launch(void* const* d_in, const int* in_sizes, int n_in,
                              void* d_out, int out_size) {
    const float* feature = (const float*)d_in[0];
    const float* coord   = (const float*)d_in[1];
    const float* scale   = (const float*)d_in[2];
    const float* kW1 = (const float*)d_in[3];
    const float* kb1 = (const float*)d_in[4];
    const float* kW2 = (const float*)d_in[5];
    const float* kb2 = (const float*)d_in[6];
    const float* vW1 = (const float*)d_in[7];
    const float* vb1 = (const float*)d_in[8];
    const float* vW2 = (const float*)d_in[9];
    const float* vb2 = (const float*)d_in[10];
    const float* qW1 = (const float*)d_in[11];
    const float* qb1 = (const float*)d_in[12];
    const float* qW2 = (const float*)d_in[13];
    const float* qb2 = (const float*)d_in[14];
    float* out = (float*)d_out;

    float *pINP, *pH, *pPK, *pPV, *pX, *pHq, *pW1t, *pb1, *pkW2t, *pvW2t, *pqW1t;
    cudaGetSymbolAddress((void**)&pINP,  g_INP);
    cudaGetSymbolAddress((void**)&pH,    g_H);
    cudaGetSymbolAddress((void**)&pPK,   g_PK);
    cudaGetSymbolAddress((void**)&pPV,   g_PV);
    cudaGetSymbolAddress((void**)&pX,    g_X);
    cudaGetSymbolAddress((void**)&pHq,   g_Hq);
    cudaGetSymbolAddress((void**)&pW1t,  g_W1t);
    cudaGetSymbolAddress((void**)&pb1,   g_b1);
    cudaGetSymbolAddress((void**)&pkW2t, g_kW2t);
    cudaGetSymbolAddress((void**)&pvW2t, g_vW2t);
    cudaGetSymbolAddress((void**)&pqW1t, g_qW1t);

    cudaFuncSetAttribute(mma_gemm<0>, cudaFuncAttributeMaxDynamicSharedMemorySize, SMEMB);
    cudaFuncSetAttribute(mma_gemm<1>, cudaFuncAttributeMaxDynamicSharedMemorySize, SMEMB);

    // 0) transpose/pad/round weights (fused W1)
    prep_weights<<<(512 * KINP + 255) / 256, 256>>>(kW1, vW1, kW2, vW2, qW1, kb1, vb1);

    // 1) gather/setup
    setup_kernel<<<NROW, 128>>>(feature, coord, scale);

    // 2) fused layer-1:  H[:, 0:512] = tf32r(relu(INP @ W1t^T + b1)), K=608
    {
        dim3 grid(4, NROW4 / 128);
        mma_gemm<0><<<grid, 256, SMEMB>>>(pINP, KINP, pW1t, pH, pb1, nullptr, 0, KINP, 512);
    }

    // 3) layer-2 MLPs:  P = kv * (H @ W2t^T + b2)    [32768 x 576], K=256
    {
        dim3 grid((CK + 127) / 128, NROW4 / 128);
        mma_gemm<1><<<grid, 256, SMEMB>>>(pH,       512, pkW2t, pPK, kb2, pINP, KINP, HID, CK);
        mma_gemm<1><<<grid, 256, SMEMB>>>(pH + 256, 512, pvW2t, pPV, vb2, pINP, KINP, HID, CK);
    }

    // 4) attention + softmax + weighted sum -> X     [8192 x 576]
    attn_kernel<<<NROW, 192>>>();

    // 5) query MLP layer 1: Hq = relu(X @ qW1t^T + qb1)  [8192 x 256], K=576
    {
        dim3 grid(2, NROW / 128);
        mma_gemm<0><<<grid, 256, SMEMB>>>(pX, CK, pqW1t, pHq, qb1, nullptr, 0, CK, HID);
    }

    // 6) output projection  [8192 x 3]
    outproj_kernel<<<NROW / 4, 128>>>(qW2, qb2, out);
}